// round 6
// baseline (speedup 1.0000x reference)
#include <cuda_runtime.h>
#include <math.h>
#include <stdint.h>

// ---------------- problem constants ----------------
#define N_INST 64
#define N_PTS  8192
#define HID    256
#define NLAY   5
#define LATENT 64

// ---------------- device scratch (static, allocation-free) ----------------
__device__ __align__(1024) float g_actA[(size_t)N_INST * N_PTS * HID]; // 512 MiB
__device__ __align__(1024) float g_actB[(size_t)N_INST * N_PTS * HID]; // 512 MiB
__device__ __align__(1024) float g_W [(size_t)N_INST * HID * HID];     // combined weights
__device__ __align__(1024) float g_Bc[(size_t)N_INST * HID];           // combined bias
__device__ float g_tv[(size_t)N_INST * NLAY * 256];    // top-k gate values
__device__ int   g_ti[(size_t)N_INST * NLAY * 256];    // top-k expert indices

struct GatePtrs {
    const float* gw[5];
    const float* gb[5];
};

// ---------------- tf32 helpers ----------------
__device__ __forceinline__ float tf32_rna(float x) {
    float h;
    asm("cvt.rna.tf32.f32 %0, %1;" : "=f"(h) : "f"(x));
    return h;
}

// mma.sync m16n8k8 tf32: D += A*B  (A row-major 16x8, B col-major 8x8, fp32 accum)
__device__ __forceinline__ void mma_tf32(float* d, const uint32_t* a, const uint32_t* b) {
    asm volatile(
        "mma.sync.aligned.m16n8k8.row.col.f32.tf32.tf32.f32 "
        "{%0,%1,%2,%3}, {%4,%5,%6,%7}, {%8,%9}, {%0,%1,%2,%3};\n"
        : "+f"(d[0]), "+f"(d[1]), "+f"(d[2]), "+f"(d[3])
        : "r"(a[0]), "r"(a[1]), "r"(a[2]), "r"(a[3]), "r"(b[0]), "r"(b[1]));
}

// ---------------- fast sin(30*x) ----------------
__device__ __forceinline__ float sin30f(float x) {
    const float INV_2PI_30 = 4.774648292756860f; // 30/(2*pi)
    float t = x * INV_2PI_30;
    float n = __fadd_rn(t, 12582912.0f);
    n = __fadd_rn(n, -12582912.0f);
    float r = t - n;
    float u = r * r;
    float p = 3.8199525797f;
    p = fmaf(p, u, -15.0946425768f);
    p = fmaf(p, u,  42.0586939449f);
    p = fmaf(p, u, -76.7058597531f);
    p = fmaf(p, u,  81.6052492761f);
    p = fmaf(p, u, -41.3417022404f);
    p = fmaf(p, u,   6.2831853072f);
    return r * p;
}

// ---------------- gate + top-k kernel ----------------
__global__ void gate_kernel(const float* __restrict__ latents, GatePtrs gp) {
    const int l = blockIdx.x;
    const int n = blockIdx.y;
    const int tid = threadIdx.x;

    const int Es[5] = {8, 16, 64, 256, 1024};
    const int Ks[5] = {4, 4, 32, 32, 256};
    const int E = Es[l];
    const int K = Ks[l];

    __shared__ float lat[LATENT];
    __shared__ float gate[1024];
    __shared__ float gabs[1024];
    __shared__ float rv[256];
    __shared__ int   ri[256];

    if (tid < LATENT) lat[tid] = latents[((size_t)n * NLAY + l) * LATENT + tid];
    __syncthreads();

    const float* gw = gp.gw[l];
    const float* gb = gp.gb[l];
    for (int e = tid; e < E; e += 256) {
        const float* row = gw + (size_t)e * LATENT;
        float s = gb[e];
        #pragma unroll 8
        for (int j = 0; j < LATENT; j++) s = fmaf(lat[j], row[j], s);
        gate[e] = s;
        gabs[e] = fabsf(s);
    }
    __syncthreads();

    for (int it = 0; it < K; it++) {
        float best = -1.0f; int bi = 1 << 30;
        for (int e = tid; e < E; e += 256) {
            float v = gabs[e];
            if (v > best) { best = v; bi = e; }
        }
        rv[tid] = best; ri[tid] = bi;
        __syncthreads();
        #pragma unroll
        for (int s = 128; s > 0; s >>= 1) {
            if (tid < s) {
                float ov = rv[tid + s]; int oi = ri[tid + s];
                if (ov > rv[tid] || (ov == rv[tid] && oi < ri[tid])) { rv[tid] = ov; ri[tid] = oi; }
            }
            __syncthreads();
        }
        int widx = ri[0];
        if (tid == 0) {
            g_tv[((size_t)n * NLAY + l) * 256 + it] = gate[widx];
            g_ti[((size_t)n * NLAY + l) * 256 + it] = widx;
            gabs[widx] = -2.0f;
        }
        __syncthreads();
    }
}

// ---------------- combine kernel (parallel over M tiles) ----------------
__global__ void combine_kernel(const float* __restrict__ wbank,
                               const float* __restrict__ bbank,
                               int l, int K, int dout, int dinn) {
    const int n = blockIdx.y;
    const int tid = threadIdx.x;
    __shared__ float sv[256];
    __shared__ int   sw[256];
    __shared__ int   sb[256];
    if (tid < K) {
        sv[tid] = g_tv[((size_t)n * NLAY + l) * 256 + tid];
        int e   = g_ti[((size_t)n * NLAY + l) * 256 + tid];
        sw[tid] = e * dout * dinn;
        sb[tid] = e * dout;
    }
    __syncthreads();

    const int M = dout * dinn;
    const int M4 = M >> 2;
    int base4 = blockIdx.x * 1024 + tid;
    #pragma unroll
    for (int it = 0; it < 4; it++) {
        int m4 = base4 + it * 256;
        if (m4 < M4) {
            float4 acc = make_float4(0.f, 0.f, 0.f, 0.f);
            for (int j = 0; j < K; j++) {
                float v = sv[j];
                float4 w = *(const float4*)(wbank + (size_t)sw[j] + m4 * 4);
                acc.x = fmaf(v, w.x, acc.x);
                acc.y = fmaf(v, w.y, acc.y);
                acc.z = fmaf(v, w.z, acc.z);
                acc.w = fmaf(v, w.w, acc.w);
            }
            *(float4*)(g_W + (size_t)n * M + m4 * 4) = acc;
        }
    }
    if (blockIdx.x == 0) {
        for (int m = tid; m < dout; m += 256) {
            float s = 0.0f;
            for (int j = 0; j < K; j++) s = fmaf(sv[j], bbank[(size_t)sb[j] + m], s);
            g_Bc[(size_t)n * dout + m] = s;
        }
    }
}

// ---------------- layer 0: d_in=2 -> 256, sin ----------------
__global__ void layer0_kernel(const float* __restrict__ coords) {
    const int n  = blockIdx.y;
    const int p0 = blockIdx.x * 64;
    const int o  = threadIdx.x;
    __shared__ float w0[HID], w1[HID], bb[HID];
    w0[o] = g_W[(size_t)n * 512 + o * 2 + 0];
    w1[o] = g_W[(size_t)n * 512 + o * 2 + 1];
    bb[o] = g_Bc[(size_t)n * HID + o];
    __syncthreads();
    const float* cn = coords + ((size_t)n * N_PTS) * 2;
    float* Y = g_actA + ((size_t)n * N_PTS) * HID;
    #pragma unroll 4
    for (int pp = 0; pp < 64; pp++) {
        int p = p0 + pp;
        float x0 = cn[(size_t)p * 2 + 0];
        float x1 = cn[(size_t)p * 2 + 1];
        float v = fmaf(x0, w0[o], fmaf(x1, w1[o], bb[o]));
        Y[(size_t)p * HID + o] = sin30f(v);
    }
}

// ---------------- hidden layers 1-3: mma.sync tf32 2-split GEMM ----------------
// Y[p][o] = sin(30*(sum_k X[p][k]*W[o][k] + B[o]))
// CTA tile 128x128, K=256 in 8 chunks of 32 (double-buffered smem + reg prefetch).
// fp32 split into (tf32 hi, tf32 lo); D = Xh*Wh + Xh*Wl + Xl*Wh on tensor pipe.
// 8 warps = 2(M) x 4(N); warp tile 64x32 = 4x4 grid of m16n8k8.
#define KSTRIDE 36                      // smem row stride (floats): conflict-free frags
#define CHUNKF  (128 * KSTRIDE)         // floats per tile array per chunk
#define GEMM_SMEM_FLOATS (128 + 2 * 4 * CHUNKF)
#define GEMM_SMEM_BYTES  (GEMM_SMEM_FLOATS * 4)   // 147968 B

__global__ void __launch_bounds__(256, 1) gemm_mma(int srcA) {
    extern __shared__ float sm[];
    float* bias = sm;
    float* bufs = sm + 128;

    const int tid  = threadIdx.x;
    const int lane = tid & 31;
    const int wid  = tid >> 5;
    const int g = lane >> 2;       // groupID (0..7)
    const int t = lane & 3;        // thread-in-group (0..3)
    const int warpM = wid & 1;     // 0..1
    const int warpN = wid >> 1;    // 0..3

    const float* Xg = srcA ? g_actA : g_actB;
    float*       Yg = srcA ? g_actB : g_actA;
    const int n  = blockIdx.z;
    const int p0 = blockIdx.x * 128;
    const int o0 = blockIdx.y * 128;
    const float* Xn = Xg + (size_t)n * N_PTS * HID;
    const float* Wn = g_W + (size_t)n * HID * HID + (size_t)o0 * HID;
    float*       Yn = Yg + (size_t)n * N_PTS * HID;

    if (tid < 128) bias[tid] = g_Bc[(size_t)n * HID + o0 + tid];

    const int lrow = tid >> 3;     // 0..31 (gmem/sts row within 32-row group)
    const int c4   = tid & 7;      // k-group of 4

    float4 rx[4], rw[4];

    auto loadregs = [&](int kc) {
        const int k0 = kc * 32;
        #pragma unroll
        for (int i = 0; i < 4; i++) {
            rx[i] = *(const float4*)(Xn + (size_t)(p0 + lrow + i * 32) * HID + k0 + c4 * 4);
            rw[i] = *(const float4*)(Wn + (size_t)(lrow + i * 32) * HID + k0 + c4 * 4);
        }
    };

    auto storebuf = [&](int b) {
        float* Xh = bufs + (size_t)b * 4 * CHUNKF;
        float* Xl = Xh + CHUNKF;
        float* Wh = Xh + 2 * CHUNKF;
        float* Wl = Xh + 3 * CHUNKF;
        #pragma unroll
        for (int i = 0; i < 4; i++) {
            const int off = (lrow + i * 32) * KSTRIDE + c4 * 4;
            float4 v = rx[i];
            float4 h, l;
            h.x = tf32_rna(v.x); l.x = tf32_rna(v.x - h.x);
            h.y = tf32_rna(v.y); l.y = tf32_rna(v.y - h.y);
            h.z = tf32_rna(v.z); l.z = tf32_rna(v.z - h.z);
            h.w = tf32_rna(v.w); l.w = tf32_rna(v.w - h.w);
            *(float4*)(Xh + off) = h;
            *(float4*)(Xl + off) = l;
            v = rw[i];
            h.x = tf32_rna(v.x); l.x = tf32_rna(v.x - h.x);
            h.y = tf32_rna(v.y); l.y = tf32_rna(v.y - h.y);
            h.z = tf32_rna(v.z); l.z = tf32_rna(v.z - h.z);
            h.w = tf32_rna(v.w); l.w = tf32_rna(v.w - h.w);
            *(float4*)(Wh + off) = h;
            *(float4*)(Wl + off) = l;
        }
    };

    float acc[4][4][4];
    #pragma unroll
    for (int i = 0; i < 4; i++)
        #pragma unroll
        for (int j = 0; j < 4; j++)
            #pragma unroll
            for (int q = 0; q < 4; q++) acc[i][j][q] = 0.0f;

    loadregs(0);
    storebuf(0);
    __syncthreads();

    for (int kc = 0; kc < 8; kc++) {
        const int b = kc & 1;
        if (kc < 7) loadregs(kc + 1);

        const float* Xh = bufs + (size_t)b * 4 * CHUNKF;
        const float* Xl = Xh + CHUNKF;
        const float* Wh = Xh + 2 * CHUNKF;
        const float* Wl = Xh + 3 * CHUNKF;

        #pragma unroll
        for (int ks = 0; ks < 4; ks++) {
            const int kb = ks * 8;
            uint32_t ah[4][4], al[4][4], bh[4][2], bl[4][2];
            #pragma unroll
            for (int i = 0; i < 4; i++) {
                const int r0 = (warpM * 64 + i * 16 + g) * KSTRIDE + kb + t;
                const int r1 = r0 + 8 * KSTRIDE;
                ah[i][0] = __float_as_uint(Xh[r0]);
                ah[i][1] = __float_as_uint(Xh[r1]);
                ah[i][2] = __float_as_uint(Xh[r0 + 4]);
                ah[i][3] = __float_as_uint(Xh[r1 + 4]);
                al[i][0] = __float_as_uint(Xl[r0]);
                al[i][1] = __float_as_uint(Xl[r1]);
                al[i][2] = __float_as_uint(Xl[r0 + 4]);
                al[i][3] = __float_as_uint(Xl[r1 + 4]);
            }
            #pragma unroll
            for (int j = 0; j < 4; j++) {
                const int cB = (warpN * 32 + j * 8 + g) * KSTRIDE + kb + t;
                bh[j][0] = __float_as_uint(Wh[cB]);
                bh[j][1] = __float_as_uint(Wh[cB + 4]);
                bl[j][0] = __float_as_uint(Wl[cB]);
                bl[j][1] = __float_as_uint(Wl[cB + 4]);
            }
            #pragma unroll
            for (int i = 0; i < 4; i++)
                #pragma unroll
                for (int j = 0; j < 4; j++) {
                    mma_tf32(acc[i][j], ah[i], bh[j]);
                    mma_tf32(acc[i][j], ah[i], bl[j]);
                    mma_tf32(acc[i][j], al[i], bh[j]);
                }
        }

        if (kc < 7) storebuf(b ^ 1);
        __syncthreads();
    }

    // epilogue: bias + sin(30x), float2 stores from C fragments
    #pragma unroll
    for (int i = 0; i < 4; i++) {
        const int rg = p0 + warpM * 64 + i * 16 + g;
        #pragma unroll
        for (int j = 0; j < 4; j++) {
            const int cl = warpN * 32 + j * 8 + t * 2;  // local col within 128
            const float b0 = bias[cl], b1 = bias[cl + 1];
            float2 v0, v1;
            v0.x = sin30f(acc[i][j][0] + b0);
            v0.y = sin30f(acc[i][j][1] + b1);
            v1.x = sin30f(acc[i][j][2] + b0);
            v1.y = sin30f(acc[i][j][3] + b1);
            *(float2*)(Yn + (size_t)rg * HID + o0 + cl)       = v0;
            *(float2*)(Yn + (size_t)(rg + 8) * HID + o0 + cl) = v1;
        }
    }
}

// ---------------- layer 4: 256 -> 3, no sin ----------------
__global__ void layer4_kernel(float* __restrict__ out) {
    const int n = blockIdx.y;
    const int warp = threadIdx.x >> 5;
    const int lane = threadIdx.x & 31;
    const int p = blockIdx.x * 8 + warp;

    __shared__ float Wsh[3 * HID];
    __shared__ float Bsh[3];
    for (int m = threadIdx.x; m < 3 * HID; m += 256) Wsh[m] = g_W[(size_t)n * 768 + m];
    if (threadIdx.x < 3) Bsh[threadIdx.x] = g_Bc[(size_t)n * 3 + threadIdx.x];
    __syncthreads();

    const float* xr = g_actB + ((size_t)n * N_PTS + p) * HID;
    float4 xa = *(const float4*)(xr + lane * 8 + 0);
    float4 xb = *(const float4*)(xr + lane * 8 + 4);

    float s[3];
    #pragma unroll
    for (int o = 0; o < 3; o++) {
        const float* w = Wsh + o * HID + lane * 8;
        float t = 0.0f;
        t = fmaf(xa.x, w[0], t); t = fmaf(xa.y, w[1], t);
        t = fmaf(xa.z, w[2], t); t = fmaf(xa.w, w[3], t);
        t = fmaf(xb.x, w[4], t); t = fmaf(xb.y, w[5], t);
        t = fmaf(xb.z, w[6], t); t = fmaf(xb.w, w[7], t);
        s[o] = t;
    }
    #pragma unroll
    for (int off = 16; off > 0; off >>= 1) {
        #pragma unroll
        for (int o = 0; o < 3; o++) s[o] += __shfl_xor_sync(0xFFFFFFFFu, s[o], off);
    }
    if (lane == 0) {
        float* op = out + ((size_t)n * N_PTS + p) * 3;
        op[0] = s[0] + Bsh[0];
        op[1] = s[1] + Bsh[1];
        op[2] = s[2] + Bsh[2];
    }
}

// ---------------- host launch ----------------
extern "C" void kernel_launch(void* const* d_in, const int* in_sizes, int n_in,
                              void* d_out, int out_size) {
    const float* latents = (const float*)d_in[0];
    const float* coords  = (const float*)d_in[1];
    const float *gw[5], *gb[5], *w[5], *b[5];

    bool interleaved = (in_sizes[3] == 8); // gb0 has 8 elements
    if (interleaved) {
        for (int i = 0; i < 5; i++) {
            gw[i] = (const float*)d_in[2 + 2 * i];
            gb[i] = (const float*)d_in[3 + 2 * i];
            w[i]  = (const float*)d_in[12 + 2 * i];
            b[i]  = (const float*)d_in[13 + 2 * i];
        }
    } else {
        for (int i = 0; i < 5; i++) {
            gw[i] = (const float*)d_in[2 + i];
            gb[i] = (const float*)d_in[7 + i];
            w[i]  = (const float*)d_in[12 + i];
            b[i]  = (const float*)d_in[17 + i];
        }
    }

    GatePtrs gp;
    for (int i = 0; i < 5; i++) { gp.gw[i] = gw[i]; gp.gb[i] = gb[i]; }

    const int Ks[5]   = {4, 4, 32, 32, 256};
    const int din[5]  = {2, 256, 256, 256, 256};
    const int dout[5] = {256, 256, 256, 256, 3};

    cudaFuncSetAttribute(gemm_mma, cudaFuncAttributeMaxDynamicSharedMemorySize,
                         GEMM_SMEM_BYTES);

    gate_kernel<<<dim3(NLAY, N_INST), 256>>>(latents, gp);

    for (int l = 0; l < NLAY; l++) {
        int M = dout[l] * din[l];
        int gx = (M + 1023) / 1024;
        combine_kernel<<<dim3(gx, N_INST), 256>>>(w[l], b[l], l, Ks[l], dout[l], din[l]);
        if (l == 0) {
            layer0_kernel<<<dim3(N_PTS / 64, N_INST), 256>>>(coords);
        } else if (l < 4) {
            int srcA = (l & 1);   // l=1: A->B, l=2: B->A, l=3: A->B
            gemm_mma<<<dim3(N_PTS / 128, 2, N_INST), 256, GEMM_SMEM_BYTES>>>(srcA);
        } else {
            layer4_kernel<<<dim3(N_PTS / 8, N_INST), 256>>>((float*)d_out);
        }
    }
}

// round 7
// speedup vs baseline: 1.0365x; 1.0365x over previous
#include <cuda_runtime.h>
#include <math.h>
#include <stdint.h>

// ---------------- problem constants ----------------
#define N_INST 64
#define N_PTS  8192
#define HID    256
#define NLAY   5
#define LATENT 64

// ---------------- device scratch (static, allocation-free) ----------------
__device__ __align__(1024) float g_actA[(size_t)N_INST * N_PTS * HID]; // 512 MiB
__device__ __align__(1024) float g_actB[(size_t)N_INST * N_PTS * HID]; // 512 MiB
__device__ __align__(1024) float g_W [(size_t)N_INST * HID * HID];     // combined weights
__device__ __align__(1024) float g_Bc[(size_t)N_INST * HID];           // combined bias
__device__ float g_tv[(size_t)N_INST * NLAY * 256];    // top-k gate values
__device__ int   g_ti[(size_t)N_INST * NLAY * 256];    // top-k expert indices

struct GatePtrs {
    const float* gw[5];
    const float* gb[5];
};

// ---------------- helpers ----------------
__device__ __forceinline__ uint32_t smem_to_u32(const void* smem_ptr) {
    uint32_t addr;
    asm("{ .reg .u64 tmp; cvta.to.shared.u64 tmp, %1; cvt.u32.u64 %0, tmp; }"
        : "=r"(addr) : "l"(smem_ptr));
    return addr;
}
__device__ __forceinline__ void cp_async16(uint32_t dst, const void* src) {
    asm volatile("cp.async.cg.shared.global [%0], [%1], 16;"
                 :: "r"(dst), "l"(src) : "memory");
}
__device__ __forceinline__ void cp_commit() {
    asm volatile("cp.async.commit_group;" ::: "memory");
}
template <int N>
__device__ __forceinline__ void cp_wait() {
    asm volatile("cp.async.wait_group %0;" :: "n"(N) : "memory");
}

__device__ __forceinline__ float tf32_rna(float x) {
    float h;
    asm("cvt.rna.tf32.f32 %0, %1;" : "=f"(h) : "f"(x));
    return h;
}

// mma.sync m16n8k8 tf32: D += A*B  (A row-major 16x8, B col-major 8x8, fp32 accum)
__device__ __forceinline__ void mma_tf32(float* d, const uint32_t* a, const uint32_t* b) {
    asm volatile(
        "mma.sync.aligned.m16n8k8.row.col.f32.tf32.tf32.f32 "
        "{%0,%1,%2,%3}, {%4,%5,%6,%7}, {%8,%9}, {%0,%1,%2,%3};\n"
        : "+f"(d[0]), "+f"(d[1]), "+f"(d[2]), "+f"(d[3])
        : "r"(a[0]), "r"(a[1]), "r"(a[2]), "r"(a[3]), "r"(b[0]), "r"(b[1]));
}

// ---------------- fast sin(30*x) ----------------
__device__ __forceinline__ float sin30f(float x) {
    const float INV_2PI_30 = 4.774648292756860f; // 30/(2*pi)
    float t = x * INV_2PI_30;
    float n = __fadd_rn(t, 12582912.0f);
    n = __fadd_rn(n, -12582912.0f);
    float r = t - n;
    float u = r * r;
    float p = 3.8199525797f;
    p = fmaf(p, u, -15.0946425768f);
    p = fmaf(p, u,  42.0586939449f);
    p = fmaf(p, u, -76.7058597531f);
    p = fmaf(p, u,  81.6052492761f);
    p = fmaf(p, u, -41.3417022404f);
    p = fmaf(p, u,   6.2831853072f);
    return r * p;
}

// ---------------- gate + top-k kernel ----------------
__global__ void gate_kernel(const float* __restrict__ latents, GatePtrs gp) {
    const int l = blockIdx.x;
    const int n = blockIdx.y;
    const int tid = threadIdx.x;

    const int Es[5] = {8, 16, 64, 256, 1024};
    const int Ks[5] = {4, 4, 32, 32, 256};
    const int E = Es[l];
    const int K = Ks[l];

    __shared__ float lat[LATENT];
    __shared__ float gate[1024];
    __shared__ float gabs[1024];
    __shared__ float rv[256];
    __shared__ int   ri[256];

    if (tid < LATENT) lat[tid] = latents[((size_t)n * NLAY + l) * LATENT + tid];
    __syncthreads();

    const float* gw = gp.gw[l];
    const float* gb = gp.gb[l];
    for (int e = tid; e < E; e += 256) {
        const float* row = gw + (size_t)e * LATENT;
        float s = gb[e];
        #pragma unroll 8
        for (int j = 0; j < LATENT; j++) s = fmaf(lat[j], row[j], s);
        gate[e] = s;
        gabs[e] = fabsf(s);
    }
    __syncthreads();

    for (int it = 0; it < K; it++) {
        float best = -1.0f; int bi = 1 << 30;
        for (int e = tid; e < E; e += 256) {
            float v = gabs[e];
            if (v > best) { best = v; bi = e; }
        }
        rv[tid] = best; ri[tid] = bi;
        __syncthreads();
        #pragma unroll
        for (int s = 128; s > 0; s >>= 1) {
            if (tid < s) {
                float ov = rv[tid + s]; int oi = ri[tid + s];
                if (ov > rv[tid] || (ov == rv[tid] && oi < ri[tid])) { rv[tid] = ov; ri[tid] = oi; }
            }
            __syncthreads();
        }
        int widx = ri[0];
        if (tid == 0) {
            g_tv[((size_t)n * NLAY + l) * 256 + it] = gate[widx];
            g_ti[((size_t)n * NLAY + l) * 256 + it] = widx;
            gabs[widx] = -2.0f;
        }
        __syncthreads();
    }
}

// ---------------- combine kernel (parallel over M tiles) ----------------
__global__ void combine_kernel(const float* __restrict__ wbank,
                               const float* __restrict__ bbank,
                               int l, int K, int dout, int dinn) {
    const int n = blockIdx.y;
    const int tid = threadIdx.x;
    __shared__ float sv[256];
    __shared__ int   sw[256];
    __shared__ int   sb[256];
    if (tid < K) {
        sv[tid] = g_tv[((size_t)n * NLAY + l) * 256 + tid];
        int e   = g_ti[((size_t)n * NLAY + l) * 256 + tid];
        sw[tid] = e * dout * dinn;
        sb[tid] = e * dout;
    }
    __syncthreads();

    const int M = dout * dinn;
    const int M4 = M >> 2;
    int base4 = blockIdx.x * 1024 + tid;
    #pragma unroll
    for (int it = 0; it < 4; it++) {
        int m4 = base4 + it * 256;
        if (m4 < M4) {
            float4 acc = make_float4(0.f, 0.f, 0.f, 0.f);
            for (int j = 0; j < K; j++) {
                float v = sv[j];
                float4 w = *(const float4*)(wbank + (size_t)sw[j] + m4 * 4);
                acc.x = fmaf(v, w.x, acc.x);
                acc.y = fmaf(v, w.y, acc.y);
                acc.z = fmaf(v, w.z, acc.z);
                acc.w = fmaf(v, w.w, acc.w);
            }
            *(float4*)(g_W + (size_t)n * M + m4 * 4) = acc;
        }
    }
    if (blockIdx.x == 0) {
        for (int m = tid; m < dout; m += 256) {
            float s = 0.0f;
            for (int j = 0; j < K; j++) s = fmaf(sv[j], bbank[(size_t)sb[j] + m], s);
            g_Bc[(size_t)n * dout + m] = s;
        }
    }
}

// ---------------- layer 0: d_in=2 -> 256, sin ----------------
__global__ void layer0_kernel(const float* __restrict__ coords) {
    const int n  = blockIdx.y;
    const int p0 = blockIdx.x * 64;
    const int o  = threadIdx.x;
    __shared__ float w0[HID], w1[HID], bb[HID];
    w0[o] = g_W[(size_t)n * 512 + o * 2 + 0];
    w1[o] = g_W[(size_t)n * 512 + o * 2 + 1];
    bb[o] = g_Bc[(size_t)n * HID + o];
    __syncthreads();
    const float* cn = coords + ((size_t)n * N_PTS) * 2;
    float* Y = g_actA + ((size_t)n * N_PTS) * HID;
    #pragma unroll 4
    for (int pp = 0; pp < 64; pp++) {
        int p = p0 + pp;
        float x0 = cn[(size_t)p * 2 + 0];
        float x1 = cn[(size_t)p * 2 + 1];
        float v = fmaf(x0, w0[o], fmaf(x1, w1[o], bb[o]));
        Y[(size_t)p * HID + o] = sin30f(v);
    }
}

// ---------------- hidden layers 1-3: mma.sync tf32 2-split GEMM ----------------
// CTA tile 128(M) x 256(N, full), K=256 in 8 chunks of 32.
// Raw fp32 tiles staged via cp.async (double-buffered); hi/lo tf32 split done
// at fragment-load time. 8 warps = 2(M) x 4(N); warp tile 64x64.
#define KSTRIDE 36                       // floats; conflict-free fragment loads
#define XBUF_F  (128 * KSTRIDE)          // 4608 floats
#define WBUF_F  (256 * KSTRIDE)          // 9216 floats
#define BUF_F   (XBUF_F + WBUF_F)        // 13824 floats
#define GEMM_SMEM_FLOATS (256 + 2 * BUF_F)
#define GEMM_SMEM_BYTES  (GEMM_SMEM_FLOATS * 4)   // 111,616 B

__global__ void __launch_bounds__(256, 1) gemm_mma(int srcA) {
    extern __shared__ float sm[];
    float* bias = sm;
    float* bufs = sm + 256;
    const uint32_t bufs_u = smem_to_u32(bufs);

    const int tid  = threadIdx.x;
    const int lane = tid & 31;
    const int wid  = tid >> 5;
    const int g = lane >> 2;       // groupID (0..7)
    const int t = lane & 3;        // thread-in-group (0..3)
    const int warpM = wid & 1;     // 0..1  (64 rows each)
    const int warpN = wid >> 1;    // 0..3  (64 cols each)

    const float* Xg = srcA ? g_actA : g_actB;
    float*       Yg = srcA ? g_actB : g_actA;
    const int n  = blockIdx.y;
    const int p0 = blockIdx.x * 128;
    const float* Xn = Xg + (size_t)n * N_PTS * HID;
    const float* Wn = g_W + (size_t)n * HID * HID;
    float*       Yn = Yg + (size_t)n * N_PTS * HID;

    // bias for all 256 outputs
    bias[tid] = g_Bc[(size_t)n * HID + tid];

    const int lrow = tid >> 3;     // 0..31
    const int c4   = tid & 7;      // 16B column group

    auto issue_chunk = [&](int kc, int b) {
        const int k0 = kc * 32;
        const uint32_t xb = bufs_u + (uint32_t)b * BUF_F * 4;
        const uint32_t wb = xb + XBUF_F * 4;
        #pragma unroll
        for (int i = 0; i < 4; i++) {             // X: 128 rows
            const int row = lrow + i * 32;
            cp_async16(xb + (uint32_t)(row * KSTRIDE + c4 * 4) * 4,
                       Xn + (size_t)(p0 + row) * HID + k0 + c4 * 4);
        }
        #pragma unroll
        for (int i = 0; i < 8; i++) {             // W: 256 rows
            const int row = lrow + i * 32;
            cp_async16(wb + (uint32_t)(row * KSTRIDE + c4 * 4) * 4,
                       Wn + (size_t)row * HID + k0 + c4 * 4);
        }
        cp_commit();
    };

    float acc[4][8][4];
    #pragma unroll
    for (int i = 0; i < 4; i++)
        #pragma unroll
        for (int j = 0; j < 8; j++)
            #pragma unroll
            for (int q = 0; q < 4; q++) acc[i][j][q] = 0.0f;

    issue_chunk(0, 0);
    issue_chunk(1, 1);

    #pragma unroll 1
    for (int kc = 0; kc < 8; kc++) {
        if (kc < 7) cp_wait<1>(); else cp_wait<0>();
        __syncthreads();

        const float* Xb = bufs + (size_t)(kc & 1) * BUF_F;
        const float* Wb = Xb + XBUF_F;

        #pragma unroll
        for (int ks = 0; ks < 4; ks++) {
            const int kb = ks * 8;
            // A fragments: load fp32, split to (hi, lo) tf32
            uint32_t ah[4][4], al[4][4];
            #pragma unroll
            for (int i = 0; i < 4; i++) {
                const int r0 = (warpM * 64 + i * 16 + g) * KSTRIDE + kb + t;
                const int r1 = r0 + 8 * KSTRIDE;
                float v0 = Xb[r0], v1 = Xb[r1], v2 = Xb[r0 + 4], v3 = Xb[r1 + 4];
                float h0 = tf32_rna(v0), h1 = tf32_rna(v1);
                float h2 = tf32_rna(v2), h3 = tf32_rna(v3);
                ah[i][0] = __float_as_uint(h0);
                ah[i][1] = __float_as_uint(h1);
                ah[i][2] = __float_as_uint(h2);
                ah[i][3] = __float_as_uint(h3);
                al[i][0] = __float_as_uint(tf32_rna(v0 - h0));
                al[i][1] = __float_as_uint(tf32_rna(v1 - h1));
                al[i][2] = __float_as_uint(tf32_rna(v2 - h2));
                al[i][3] = __float_as_uint(tf32_rna(v3 - h3));
            }
            // B fragments per j, then 3-term MMAs over i
            #pragma unroll
            for (int j = 0; j < 8; j++) {
                const int cB = (warpN * 64 + j * 8 + g) * KSTRIDE + kb + t;
                float w0 = Wb[cB], w1 = Wb[cB + 4];
                float wh0 = tf32_rna(w0), wh1 = tf32_rna(w1);
                uint32_t bh[2], bl[2];
                bh[0] = __float_as_uint(wh0);
                bh[1] = __float_as_uint(wh1);
                bl[0] = __float_as_uint(tf32_rna(w0 - wh0));
                bl[1] = __float_as_uint(tf32_rna(w1 - wh1));
                #pragma unroll
                for (int i = 0; i < 4; i++) {
                    mma_tf32(acc[i][j], ah[i], bh);
                    mma_tf32(acc[i][j], ah[i], bl);
                    mma_tf32(acc[i][j], al[i], bh);
                }
            }
        }

        __syncthreads();   // everyone done reading buf (kc&1) before refill
        if (kc + 2 < 8) issue_chunk(kc + 2, kc & 1);
    }

    // epilogue: bias + sin(30x), float2 stores from C fragments
    #pragma unroll
    for (int i = 0; i < 4; i++) {
        const int rg = p0 + warpM * 64 + i * 16 + g;
        #pragma unroll
        for (int j = 0; j < 8; j++) {
            const int cl = warpN * 64 + j * 8 + t * 2;
            const float b0 = bias[cl], b1 = bias[cl + 1];
            float2 v0, v1;
            v0.x = sin30f(acc[i][j][0] + b0);
            v0.y = sin30f(acc[i][j][1] + b1);
            v1.x = sin30f(acc[i][j][2] + b0);
            v1.y = sin30f(acc[i][j][3] + b1);
            *(float2*)(Yn + (size_t)rg * HID + cl)       = v0;
            *(float2*)(Yn + (size_t)(rg + 8) * HID + cl) = v1;
        }
    }
}

// ---------------- layer 4: 256 -> 3, no sin ----------------
__global__ void layer4_kernel(float* __restrict__ out) {
    const int n = blockIdx.y;
    const int warp = threadIdx.x >> 5;
    const int lane = threadIdx.x & 31;
    const int p = blockIdx.x * 8 + warp;

    __shared__ float Wsh[3 * HID];
    __shared__ float Bsh[3];
    for (int m = threadIdx.x; m < 3 * HID; m += 256) Wsh[m] = g_W[(size_t)n * 768 + m];
    if (threadIdx.x < 3) Bsh[threadIdx.x] = g_Bc[(size_t)n * 3 + threadIdx.x];
    __syncthreads();

    const float* xr = g_actB + ((size_t)n * N_PTS + p) * HID;
    float4 xa = *(const float4*)(xr + lane * 8 + 0);
    float4 xb = *(const float4*)(xr + lane * 8 + 4);

    float s[3];
    #pragma unroll
    for (int o = 0; o < 3; o++) {
        const float* w = Wsh + o * HID + lane * 8;
        float t = 0.0f;
        t = fmaf(xa.x, w[0], t); t = fmaf(xa.y, w[1], t);
        t = fmaf(xa.z, w[2], t); t = fmaf(xa.w, w[3], t);
        t = fmaf(xb.x, w[4], t); t = fmaf(xb.y, w[5], t);
        t = fmaf(xb.z, w[6], t); t = fmaf(xb.w, w[7], t);
        s[o] = t;
    }
    #pragma unroll
    for (int off = 16; off > 0; off >>= 1) {
        #pragma unroll
        for (int o = 0; o < 3; o++) s[o] += __shfl_xor_sync(0xFFFFFFFFu, s[o], off);
    }
    if (lane == 0) {
        float* op = out + ((size_t)n * N_PTS + p) * 3;
        op[0] = s[0] + Bsh[0];
        op[1] = s[1] + Bsh[1];
        op[2] = s[2] + Bsh[2];
    }
}

// ---------------- host launch ----------------
extern "C" void kernel_launch(void* const* d_in, const int* in_sizes, int n_in,
                              void* d_out, int out_size) {
    const float* latents = (const float*)d_in[0];
    const float* coords  = (const float*)d_in[1];
    const float *gw[5], *gb[5], *w[5], *b[5];

    bool interleaved = (in_sizes[3] == 8); // gb0 has 8 elements
    if (interleaved) {
        for (int i = 0; i < 5; i++) {
            gw[i] = (const float*)d_in[2 + 2 * i];
            gb[i] = (const float*)d_in[3 + 2 * i];
            w[i]  = (const float*)d_in[12 + 2 * i];
            b[i]  = (const float*)d_in[13 + 2 * i];
        }
    } else {
        for (int i = 0; i < 5; i++) {
            gw[i] = (const float*)d_in[2 + i];
            gb[i] = (const float*)d_in[7 + i];
            w[i]  = (const float*)d_in[12 + i];
            b[i]  = (const float*)d_in[17 + i];
        }
    }

    GatePtrs gp;
    for (int i = 0; i < 5; i++) { gp.gw[i] = gw[i]; gp.gb[i] = gb[i]; }

    const int Ks[5]   = {4, 4, 32, 32, 256};
    const int din[5]  = {2, 256, 256, 256, 256};
    const int dout[5] = {256, 256, 256, 256, 3};

    cudaFuncSetAttribute(gemm_mma, cudaFuncAttributeMaxDynamicSharedMemorySize,
                         GEMM_SMEM_BYTES);

    gate_kernel<<<dim3(NLAY, N_INST), 256>>>(latents, gp);

    for (int l = 0; l < NLAY; l++) {
        int M = dout[l] * din[l];
        int gx = (M + 1023) / 1024;
        combine_kernel<<<dim3(gx, N_INST), 256>>>(w[l], b[l], l, Ks[l], dout[l], din[l]);
        if (l == 0) {
            layer0_kernel<<<dim3(N_PTS / 64, N_INST), 256>>>(coords);
        } else if (l < 4) {
            int srcA = (l & 1);   // l=1: A->B, l=2: B->A, l=3: A->B
            gemm_mma<<<dim3(N_PTS / 128, N_INST), 256, GEMM_SMEM_BYTES>>>(srcA);
        } else {
            layer4_kernel<<<dim3(N_PTS / 8, N_INST), 256>>>((float*)d_out);
        }
    }
}

// round 8
// speedup vs baseline: 1.4538x; 1.4027x over previous
#include <cuda_runtime.h>
#include <cuda_fp16.h>
#include <math.h>
#include <stdint.h>

// ---------------- problem constants ----------------
#define N_INST 64
#define N_PTS  8192
#define HID    256
#define NLAY   5
#define LATENT 64

// ---------------- device scratch (static, allocation-free) ----------------
__device__ __align__(1024) float g_actA[(size_t)N_INST * N_PTS * HID]; // 512 MiB
__device__ __align__(1024) float g_actB[(size_t)N_INST * N_PTS * HID]; // 512 MiB
__device__ __align__(1024) float g_W [(size_t)N_INST * HID * HID];     // combined weights
__device__ __align__(1024) float g_Bc[(size_t)N_INST * HID];           // combined bias
__device__ float g_tv[(size_t)N_INST * NLAY * 256];    // top-k gate values
__device__ int   g_ti[(size_t)N_INST * NLAY * 256];    // top-k expert indices

struct GatePtrs {
    const float* gw[5];
    const float* gb[5];
};

// ---------------- helpers ----------------
__device__ __forceinline__ uint32_t smem_to_u32(const void* smem_ptr) {
    uint32_t addr;
    asm("{ .reg .u64 tmp; cvta.to.shared.u64 tmp, %1; cvt.u32.u64 %0, tmp; }"
        : "=r"(addr) : "l"(smem_ptr));
    return addr;
}
__device__ __forceinline__ void cp_async16(uint32_t dst, const void* src) {
    asm volatile("cp.async.cg.shared.global [%0], [%1], 16;"
                 :: "r"(dst), "l"(src) : "memory");
}
__device__ __forceinline__ void cp_commit() {
    asm volatile("cp.async.commit_group;" ::: "memory");
}
template <int N>
__device__ __forceinline__ void cp_wait() {
    asm volatile("cp.async.wait_group %0;" :: "n"(N) : "memory");
}

// fp16 Dekker split: x = hi + lo with hi,lo fp16 (11-bit each -> ~22-bit pair)
__device__ __forceinline__ void split_h2(float a, float b, uint32_t& hi, uint32_t& lo) {
    __half2 h = __floats2half2_rn(a, b);       // low = a, high = b
    float2 hf = __half22float2(h);
    __half2 l = __floats2half2_rn(a - hf.x, b - hf.y);
    hi = *reinterpret_cast<uint32_t*>(&h);
    lo = *reinterpret_cast<uint32_t*>(&l);
}

// mma.sync m16n8k16 fp16: D += A*B  (A row-major 16x16, B col-major 16x8, fp32 accum)
__device__ __forceinline__ void mma_f16(float* d, const uint32_t* a, const uint32_t* b) {
    asm volatile(
        "mma.sync.aligned.m16n8k16.row.col.f32.f16.f16.f32 "
        "{%0,%1,%2,%3}, {%4,%5,%6,%7}, {%8,%9}, {%0,%1,%2,%3};\n"
        : "+f"(d[0]), "+f"(d[1]), "+f"(d[2]), "+f"(d[3])
        : "r"(a[0]), "r"(a[1]), "r"(a[2]), "r"(a[3]), "r"(b[0]), "r"(b[1]));
}

// ---------------- fast sin(30*x) ----------------
__device__ __forceinline__ float sin30f(float x) {
    const float INV_2PI_30 = 4.774648292756860f; // 30/(2*pi)
    float t = x * INV_2PI_30;
    float n = __fadd_rn(t, 12582912.0f);
    n = __fadd_rn(n, -12582912.0f);
    float r = t - n;
    float u = r * r;
    float p = 3.8199525797f;
    p = fmaf(p, u, -15.0946425768f);
    p = fmaf(p, u,  42.0586939449f);
    p = fmaf(p, u, -76.7058597531f);
    p = fmaf(p, u,  81.6052492761f);
    p = fmaf(p, u, -41.3417022404f);
    p = fmaf(p, u,   6.2831853072f);
    return r * p;
}

// ---------------- gate + top-k kernel ----------------
__global__ void gate_kernel(const float* __restrict__ latents, GatePtrs gp) {
    const int l = blockIdx.x;
    const int n = blockIdx.y;
    const int tid = threadIdx.x;

    const int Es[5] = {8, 16, 64, 256, 1024};
    const int Ks[5] = {4, 4, 32, 32, 256};
    const int E = Es[l];
    const int K = Ks[l];

    __shared__ float lat[LATENT];
    __shared__ float gate[1024];
    __shared__ float gabs[1024];
    __shared__ float rv[256];
    __shared__ int   ri[256];

    if (tid < LATENT) lat[tid] = latents[((size_t)n * NLAY + l) * LATENT + tid];
    __syncthreads();

    const float* gw = gp.gw[l];
    const float* gb = gp.gb[l];
    for (int e = tid; e < E; e += 256) {
        const float* row = gw + (size_t)e * LATENT;
        float s = gb[e];
        #pragma unroll 8
        for (int j = 0; j < LATENT; j++) s = fmaf(lat[j], row[j], s);
        gate[e] = s;
        gabs[e] = fabsf(s);
    }
    __syncthreads();

    for (int it = 0; it < K; it++) {
        float best = -1.0f; int bi = 1 << 30;
        for (int e = tid; e < E; e += 256) {
            float v = gabs[e];
            if (v > best) { best = v; bi = e; }
        }
        rv[tid] = best; ri[tid] = bi;
        __syncthreads();
        #pragma unroll
        for (int s = 128; s > 0; s >>= 1) {
            if (tid < s) {
                float ov = rv[tid + s]; int oi = ri[tid + s];
                if (ov > rv[tid] || (ov == rv[tid] && oi < ri[tid])) { rv[tid] = ov; ri[tid] = oi; }
            }
            __syncthreads();
        }
        int widx = ri[0];
        if (tid == 0) {
            g_tv[((size_t)n * NLAY + l) * 256 + it] = gate[widx];
            g_ti[((size_t)n * NLAY + l) * 256 + it] = widx;
            gabs[widx] = -2.0f;
        }
        __syncthreads();
    }
}

// ---------------- combine kernel (parallel over M tiles) ----------------
__global__ void combine_kernel(const float* __restrict__ wbank,
                               const float* __restrict__ bbank,
                               int l, int K, int dout, int dinn) {
    const int n = blockIdx.y;
    const int tid = threadIdx.x;
    __shared__ float sv[256];
    __shared__ int   sw[256];
    __shared__ int   sb[256];
    if (tid < K) {
        sv[tid] = g_tv[((size_t)n * NLAY + l) * 256 + tid];
        int e   = g_ti[((size_t)n * NLAY + l) * 256 + tid];
        sw[tid] = e * dout * dinn;
        sb[tid] = e * dout;
    }
    __syncthreads();

    const int M = dout * dinn;
    const int M4 = M >> 2;
    int base4 = blockIdx.x * 1024 + tid;
    #pragma unroll
    for (int it = 0; it < 4; it++) {
        int m4 = base4 + it * 256;
        if (m4 < M4) {
            float4 acc = make_float4(0.f, 0.f, 0.f, 0.f);
            for (int j = 0; j < K; j++) {
                float v = sv[j];
                float4 w = *(const float4*)(wbank + (size_t)sw[j] + m4 * 4);
                acc.x = fmaf(v, w.x, acc.x);
                acc.y = fmaf(v, w.y, acc.y);
                acc.z = fmaf(v, w.z, acc.z);
                acc.w = fmaf(v, w.w, acc.w);
            }
            *(float4*)(g_W + (size_t)n * M + m4 * 4) = acc;
        }
    }
    if (blockIdx.x == 0) {
        for (int m = tid; m < dout; m += 256) {
            float s = 0.0f;
            for (int j = 0; j < K; j++) s = fmaf(sv[j], bbank[(size_t)sb[j] + m], s);
            g_Bc[(size_t)n * dout + m] = s;
        }
    }
}

// ---------------- layer 0: d_in=2 -> 256, sin ----------------
__global__ void layer0_kernel(const float* __restrict__ coords) {
    const int n  = blockIdx.y;
    const int p0 = blockIdx.x * 64;
    const int o  = threadIdx.x;
    __shared__ float w0[HID], w1[HID], bb[HID];
    w0[o] = g_W[(size_t)n * 512 + o * 2 + 0];
    w1[o] = g_W[(size_t)n * 512 + o * 2 + 1];
    bb[o] = g_Bc[(size_t)n * HID + o];
    __syncthreads();
    const float* cn = coords + ((size_t)n * N_PTS) * 2;
    float* Y = g_actA + ((size_t)n * N_PTS) * HID;
    #pragma unroll 4
    for (int pp = 0; pp < 64; pp++) {
        int p = p0 + pp;
        float x0 = cn[(size_t)p * 2 + 0];
        float x1 = cn[(size_t)p * 2 + 1];
        float v = fmaf(x0, w0[o], fmaf(x1, w1[o], bb[o]));
        Y[(size_t)p * HID + o] = sin30f(v);
    }
}

// ---------------- hidden layers 1-3: mma.sync fp16 2-split GEMM ----------------
// CTA tile 128(M) x 256(N, full), K=256 in 8 chunks of 32.
// Raw fp32 tiles staged via cp.async (double-buffered); fp16 hi/lo split done
// at fragment-load time. 8 warps = 2(M) x 4(N); warp tile 64x64.
// D = Xh*Wh + Xh*Wl + Xl*Wh via m16n8k16 (2048 MAC/instr).
#define KSTRIDE 36                       // floats
#define XBUF_F  (128 * KSTRIDE)          // 4608 floats
#define WBUF_F  (256 * KSTRIDE)          // 9216 floats
#define BUF_F   (XBUF_F + WBUF_F)        // 13824 floats
#define GEMM_SMEM_FLOATS (256 + 2 * BUF_F)
#define GEMM_SMEM_BYTES  (GEMM_SMEM_FLOATS * 4)   // 111,616 B

__global__ void __launch_bounds__(256, 1) gemm_mma(int srcA) {
    extern __shared__ float sm[];
    float* bias = sm;
    float* bufs = sm + 256;
    const uint32_t bufs_u = smem_to_u32(bufs);

    const int tid  = threadIdx.x;
    const int lane = tid & 31;
    const int wid  = tid >> 5;
    const int g = lane >> 2;       // groupID (0..7)
    const int t = lane & 3;        // thread-in-group (0..3)
    const int warpM = wid & 1;     // 0..1  (64 rows each)
    const int warpN = wid >> 1;    // 0..3  (64 cols each)

    const float* Xg = srcA ? g_actA : g_actB;
    float*       Yg = srcA ? g_actB : g_actA;
    const int n  = blockIdx.y;
    const int p0 = blockIdx.x * 128;
    const float* Xn = Xg + (size_t)n * N_PTS * HID;
    const float* Wn = g_W + (size_t)n * HID * HID;
    float*       Yn = Yg + (size_t)n * N_PTS * HID;

    // bias for all 256 outputs
    bias[tid] = g_Bc[(size_t)n * HID + tid];

    const int lrow = tid >> 3;     // 0..31
    const int c4   = tid & 7;      // 16B column group

    auto issue_chunk = [&](int kc, int b) {
        const int k0 = kc * 32;
        const uint32_t xb = bufs_u + (uint32_t)b * BUF_F * 4;
        const uint32_t wb = xb + XBUF_F * 4;
        #pragma unroll
        for (int i = 0; i < 4; i++) {             // X: 128 rows
            const int row = lrow + i * 32;
            cp_async16(xb + (uint32_t)(row * KSTRIDE + c4 * 4) * 4,
                       Xn + (size_t)(p0 + row) * HID + k0 + c4 * 4);
        }
        #pragma unroll
        for (int i = 0; i < 8; i++) {             // W: 256 rows
            const int row = lrow + i * 32;
            cp_async16(wb + (uint32_t)(row * KSTRIDE + c4 * 4) * 4,
                       Wn + (size_t)row * HID + k0 + c4 * 4);
        }
        cp_commit();
    };

    float acc[4][8][4];
    #pragma unroll
    for (int i = 0; i < 4; i++)
        #pragma unroll
        for (int j = 0; j < 8; j++)
            #pragma unroll
            for (int q = 0; q < 4; q++) acc[i][j][q] = 0.0f;

    issue_chunk(0, 0);
    issue_chunk(1, 1);

    #pragma unroll 1
    for (int kc = 0; kc < 8; kc++) {
        if (kc < 7) cp_wait<1>(); else cp_wait<0>();
        __syncthreads();

        const float* Xb = bufs + (size_t)(kc & 1) * BUF_F;
        const float* Wb = Xb + XBUF_F;

        #pragma unroll
        for (int ks = 0; ks < 2; ks++) {          // two k16 steps per 32-chunk
            const int kb = ks * 16;
            // A fragments: m16n8k16 layout
            //  a0={A[g][2t],A[g][2t+1]} a1={A[g+8][..]} a2={A[g][2t+8],..} a3={A[g+8][2t+8],..}
            uint32_t ah[4][4], al[4][4];
            #pragma unroll
            for (int i = 0; i < 4; i++) {
                const int r0 = (warpM * 64 + i * 16 + g) * KSTRIDE + kb + 2 * t;
                const int r1 = r0 + 8 * KSTRIDE;
                float2 v00 = *(const float2*)(Xb + r0);
                float2 v01 = *(const float2*)(Xb + r0 + 8);
                float2 v10 = *(const float2*)(Xb + r1);
                float2 v11 = *(const float2*)(Xb + r1 + 8);
                split_h2(v00.x, v00.y, ah[i][0], al[i][0]);
                split_h2(v10.x, v10.y, ah[i][1], al[i][1]);
                split_h2(v01.x, v01.y, ah[i][2], al[i][2]);
                split_h2(v11.x, v11.y, ah[i][3], al[i][3]);
            }
            // B fragments per j: b0={B[2t][g],B[2t+1][g]} b1={B[2t+8][g],B[2t+9][g]}
            // with B[k][o] = W[o][k]  (W rows are outputs, k contiguous)
            #pragma unroll
            for (int j = 0; j < 8; j++) {
                const int cB = (warpN * 64 + j * 8 + g) * KSTRIDE + kb + 2 * t;
                float2 w0 = *(const float2*)(Wb + cB);
                float2 w1 = *(const float2*)(Wb + cB + 8);
                uint32_t bh[2], bl[2];
                split_h2(w0.x, w0.y, bh[0], bl[0]);
                split_h2(w1.x, w1.y, bh[1], bl[1]);
                #pragma unroll
                for (int i = 0; i < 4; i++) {
                    mma_f16(acc[i][j], ah[i], bh);
                    mma_f16(acc[i][j], ah[i], bl);
                    mma_f16(acc[i][j], al[i], bh);
                }
            }
        }

        __syncthreads();   // everyone done reading buf (kc&1) before refill
        if (kc + 2 < 8) issue_chunk(kc + 2, kc & 1);
    }

    // epilogue: bias + sin(30x), float2 stores from C fragments
    #pragma unroll
    for (int i = 0; i < 4; i++) {
        const int rg = p0 + warpM * 64 + i * 16 + g;
        #pragma unroll
        for (int j = 0; j < 8; j++) {
            const int cl = warpN * 64 + j * 8 + t * 2;
            const float b0 = bias[cl], b1 = bias[cl + 1];
            float2 v0, v1;
            v0.x = sin30f(acc[i][j][0] + b0);
            v0.y = sin30f(acc[i][j][1] + b1);
            v1.x = sin30f(acc[i][j][2] + b0);
            v1.y = sin30f(acc[i][j][3] + b1);
            *(float2*)(Yn + (size_t)rg * HID + cl)       = v0;
            *(float2*)(Yn + (size_t)(rg + 8) * HID + cl) = v1;
        }
    }
}

// ---------------- layer 4: 256 -> 3, no sin ----------------
__global__ void layer4_kernel(float* __restrict__ out) {
    const int n = blockIdx.y;
    const int warp = threadIdx.x >> 5;
    const int lane = threadIdx.x & 31;
    const int p = blockIdx.x * 8 + warp;

    __shared__ float Wsh[3 * HID];
    __shared__ float Bsh[3];
    for (int m = threadIdx.x; m < 3 * HID; m += 256) Wsh[m] = g_W[(size_t)n * 768 + m];
    if (threadIdx.x < 3) Bsh[threadIdx.x] = g_Bc[(size_t)n * 3 + threadIdx.x];
    __syncthreads();

    const float* xr = g_actB + ((size_t)n * N_PTS + p) * HID;
    float4 xa = *(const float4*)(xr + lane * 8 + 0);
    float4 xb = *(const float4*)(xr + lane * 8 + 4);

    float s[3];
    #pragma unroll
    for (int o = 0; o < 3; o++) {
        const float* w = Wsh + o * HID + lane * 8;
        float t = 0.0f;
        t = fmaf(xa.x, w[0], t); t = fmaf(xa.y, w[1], t);
        t = fmaf(xa.z, w[2], t); t = fmaf(xa.w, w[3], t);
        t = fmaf(xb.x, w[4], t); t = fmaf(xb.y, w[5], t);
        t = fmaf(xb.z, w[6], t); t = fmaf(xb.w, w[7], t);
        s[o] = t;
    }
    #pragma unroll
    for (int off = 16; off > 0; off >>= 1) {
        #pragma unroll
        for (int o = 0; o < 3; o++) s[o] += __shfl_xor_sync(0xFFFFFFFFu, s[o], off);
    }
    if (lane == 0) {
        float* op = out + ((size_t)n * N_PTS + p) * 3;
        op[0] = s[0] + Bsh[0];
        op[1] = s[1] + Bsh[1];
        op[2] = s[2] + Bsh[2];
    }
}

// ---------------- host launch ----------------
extern "C" void kernel_launch(void* const* d_in, const int* in_sizes, int n_in,
                              void* d_out, int out_size) {
    const float* latents = (const float*)d_in[0];
    const float* coords  = (const float*)d_in[1];
    const float *gw[5], *gb[5], *w[5], *b[5];

    bool interleaved = (in_sizes[3] == 8); // gb0 has 8 elements
    if (interleaved) {
        for (int i = 0; i < 5; i++) {
            gw[i] = (const float*)d_in[2 + 2 * i];
            gb[i] = (const float*)d_in[3 + 2 * i];
            w[i]  = (const float*)d_in[12 + 2 * i];
            b[i]  = (const float*)d_in[13 + 2 * i];
        }
    } else {
        for (int i = 0; i < 5; i++) {
            gw[i] = (const float*)d_in[2 + i];
            gb[i] = (const float*)d_in[7 + i];
            w[i]  = (const float*)d_in[12 + i];
            b[i]  = (const float*)d_in[17 + i];
        }
    }

    GatePtrs gp;
    for (int i = 0; i < 5; i++) { gp.gw[i] = gw[i]; gp.gb[i] = gb[i]; }

    const int Ks[5]   = {4, 4, 32, 32, 256};
    const int din[5]  = {2, 256, 256, 256, 256};
    const int dout[5] = {256, 256, 256, 256, 3};

    cudaFuncSetAttribute(gemm_mma, cudaFuncAttributeMaxDynamicSharedMemorySize,
                         GEMM_SMEM_BYTES);

    gate_kernel<<<dim3(NLAY, N_INST), 256>>>(latents, gp);

    for (int l = 0; l < NLAY; l++) {
        int M = dout[l] * din[l];
        int gx = (M + 1023) / 1024;
        combine_kernel<<<dim3(gx, N_INST), 256>>>(w[l], b[l], l, Ks[l], dout[l], din[l]);
        if (l == 0) {
            layer0_kernel<<<dim3(N_PTS / 64, N_INST), 256>>>(coords);
        } else if (l < 4) {
            int srcA = (l & 1);   // l=1: A->B, l=2: B->A, l=3: A->B
            gemm_mma<<<dim3(N_PTS / 128, N_INST), 256, GEMM_SMEM_BYTES>>>(srcA);
        } else {
            layer4_kernel<<<dim3(N_PTS / 8, N_INST), 256>>>((float*)d_out);
        }
    }
}